// round 2
// baseline (speedup 1.0000x reference)
#include <cuda_runtime.h>
#include <cuda_bf16.h>

#define BB 32
#define TT 1024
#define HH 384
#define MEL 4096
#define H4 (HH/4)   // 96 float4 per frame

// scratch (allocation-free rule: device globals)
__device__ int g_idx[BB * MEL];
__device__ int g_dec[BB];

// ---------------------------------------------------------------------------
// Kernel 1: per-batch inclusive scan of durations, dec_lens, frame->token map
// one block per batch, 1024 threads (one per token)
// ---------------------------------------------------------------------------
__global__ void __launch_bounds__(TT) prep_kernel(const int* __restrict__ durations)
{
    const int b = blockIdx.x;
    const int t = threadIdx.x;
    const int lane = t & 31;
    const int wid  = t >> 5;

    int rep = durations[b * TT + t];       // PACE==1.0, ints: round(d/1)=d
    if (rep < 0) rep = 0;

    // warp inclusive scan
    int v = rep;
    #pragma unroll
    for (int o = 1; o < 32; o <<= 1) {
        int n = __shfl_up_sync(0xFFFFFFFFu, v, o);
        if (lane >= o) v += n;
    }

    __shared__ int wsum[32];
    __shared__ int s_total;
    if (lane == 31) wsum[wid] = v;
    __syncthreads();
    if (wid == 0) {
        int s = wsum[lane];
        #pragma unroll
        for (int o = 1; o < 32; o <<= 1) {
            int n = __shfl_up_sync(0xFFFFFFFFu, s, o);
            if (lane >= o) s += n;
        }
        wsum[lane] = s;
    }
    __syncthreads();

    const int csum = v + (wid > 0 ? wsum[wid - 1] : 0);  // inclusive cumsum
    if (t == TT - 1) s_total = csum;
    __syncthreads();

    const int dlen = min(s_total, MEL);
    if (t == 0) g_dec[b] = dlen;

    // scatter: token t owns frames [csum-rep, csum), clamped to MEL
    int start = csum - rep;
    int end   = min(csum, MEL);
    for (int j = start; j < end; ++j)
        g_idx[b * MEL + j] = t;
}

// ---------------------------------------------------------------------------
// Kernel 2: fused conditioning-add + gather-expand. One thread per out float4.
// ---------------------------------------------------------------------------
__global__ void __launch_bounds__(256) expand_kernel(
    const float* __restrict__ enc,     // [B,T,H]
    const float* __restrict__ pitch,   // [B,1,T]
    const float* __restrict__ energy,  // [B,1,T]
    const float* __restrict__ pw,      // [H,1,3]
    const float* __restrict__ pb,      // [H]
    const float* __restrict__ ew,      // [H,1,3]
    const float* __restrict__ eb,      // [H]
    float* __restrict__ out)           // [B,MEL,H]
{
    const long long i = (long long)blockIdx.x * blockDim.x + threadIdx.x;
    const long long TOTAL4 = (long long)BB * MEL * H4;
    if (i >= TOTAL4) return;

    const int q = (int)(i % H4);          // float4 slot within H
    const long long f = i / H4;           // global frame index
    const int j = (int)(f & (MEL - 1));   // MEL = 4096 power of two
    const int b = (int)(f >> 12);

    float4 res = make_float4(0.f, 0.f, 0.f, 0.f);

    if (j < g_dec[b]) {
        const int tok = g_idx[f];

        // enc gather
        const float4 e4 = *(const float4*)(enc + ((long long)b * TT + tok) * HH + 4 * q);

        // conv windows (SAME, zero pad)
        const float* pr = pitch  + (long long)b * TT;
        const float* er = energy + (long long)b * TT;
        const float pm1 = (tok > 0)      ? pr[tok - 1] : 0.f;
        const float p0  =                  pr[tok];
        const float pp1 = (tok < TT - 1) ? pr[tok + 1] : 0.f;
        const float em1 = (tok > 0)      ? er[tok - 1] : 0.f;
        const float e0  =                  er[tok];
        const float ep1 = (tok < TT - 1) ? er[tok + 1] : 0.f;

        // weights: [H][3] row-major -> 12 contiguous floats per float4-slot
        const float4* pwv = (const float4*)(pw + 12 * q);
        const float4 w0 = pwv[0], w1 = pwv[1], w2 = pwv[2];
        const float4* ewv = (const float4*)(ew + 12 * q);
        const float4 u0 = ewv[0], u1 = ewv[1], u2 = ewv[2];
        const float4 pbv = ((const float4*)pb)[q];
        const float4 ebv = ((const float4*)eb)[q];

        res.x = e4.x + pbv.x + ebv.x
              + pm1 * w0.x + p0 * w0.y + pp1 * w0.z
              + em1 * u0.x + e0 * u0.y + ep1 * u0.z;
        res.y = e4.y + pbv.y + ebv.y
              + pm1 * w0.w + p0 * w1.x + pp1 * w1.y
              + em1 * u0.w + e0 * u1.x + ep1 * u1.y;
        res.z = e4.z + pbv.z + ebv.z
              + pm1 * w1.z + p0 * w1.w + pp1 * w2.x
              + em1 * u1.z + e0 * u1.w + ep1 * u2.x;
        res.w = e4.w + pbv.w + ebv.w
              + pm1 * w2.y + p0 * w2.z + pp1 * w2.w
              + em1 * u2.y + e0 * u2.z + ep1 * u2.w;
    }

    ((float4*)out)[i] = res;
}

// ---------------------------------------------------------------------------
// Tail: dec_lens appended to output as float values
// ---------------------------------------------------------------------------
__global__ void dec_tail_kernel(float* __restrict__ out_tail)
{
    const int b = threadIdx.x;
    if (b < BB) out_tail[b] = (float)g_dec[b];
}

extern "C" void kernel_launch(void* const* d_in, const int* in_sizes, int n_in,
                              void* d_out, int out_size)
{
    const float* enc    = (const float*)d_in[0];
    const float* pitch  = (const float*)d_in[1];
    const float* energy = (const float*)d_in[2];
    const float* pw     = (const float*)d_in[3];
    const float* pb     = (const float*)d_in[4];
    const float* ew     = (const float*)d_in[5];
    const float* eb     = (const float*)d_in[6];
    const int*   dur    = (const int*)d_in[7];
    float* out = (float*)d_out;

    prep_kernel<<<BB, TT>>>(dur);

    const long long TOTAL4 = (long long)BB * MEL * H4;   // 12,582,912
    const int threads = 256;
    const int blocks = (int)((TOTAL4 + threads - 1) / threads);
    expand_kernel<<<blocks, threads>>>(enc, pitch, energy, pw, pb, ew, eb, out);

    const long long mainN = (long long)BB * MEL * HH;    // 50,331,648
    if ((long long)out_size >= mainN + BB) {
        dec_tail_kernel<<<1, 32>>>(out + mainN);
    }
}

// round 3
// speedup vs baseline: 1.9981x; 1.9981x over previous
#include <cuda_runtime.h>
#include <cuda_bf16.h>

#define BB 32
#define TT 1024
#define HH 384
#define MEL 4096
#define H4 (HH/4)   // 96 float4 per frame

// scratch (allocation-free rule: device globals)
__device__ int g_start[BB * TT];   // exclusive cumsum of reps
__device__ int g_dec[BB];

// ---------------------------------------------------------------------------
// Kernel 1: per-batch scan of durations -> exclusive start offsets + dec_lens
// ---------------------------------------------------------------------------
__global__ void __launch_bounds__(TT) prep_kernel(const int* __restrict__ durations)
{
    const int b = blockIdx.x;
    const int t = threadIdx.x;
    const int lane = t & 31;
    const int wid  = t >> 5;

    int rep = durations[b * TT + t];   // PACE==1.0, ints: round(d/1)=d
    if (rep < 0) rep = 0;

    // warp inclusive scan
    int v = rep;
    #pragma unroll
    for (int o = 1; o < 32; o <<= 1) {
        int n = __shfl_up_sync(0xFFFFFFFFu, v, o);
        if (lane >= o) v += n;
    }

    __shared__ int wsum[32];
    __shared__ int s_total;
    if (lane == 31) wsum[wid] = v;
    __syncthreads();
    if (wid == 0) {
        int s = wsum[lane];
        #pragma unroll
        for (int o = 1; o < 32; o <<= 1) {
            int n = __shfl_up_sync(0xFFFFFFFFu, s, o);
            if (lane >= o) s += n;
        }
        wsum[lane] = s;
    }
    __syncthreads();

    const int csum = v + (wid > 0 ? wsum[wid - 1] : 0);  // inclusive
    if (t == TT - 1) s_total = csum;
    __syncthreads();

    g_start[b * TT + t] = csum - rep;                    // exclusive
    if (t == 0) g_dec[b] = min(s_total, MEL);
}

// ---------------------------------------------------------------------------
// Kernel 2: per-token conditioned vector, streamed to its rep frames.
// One block = one (b, token). 96 threads = one float4 slot each.
// ---------------------------------------------------------------------------
__global__ void __launch_bounds__(96) expand_kernel(
    const float* __restrict__ enc,     // [B,T,H]
    const float* __restrict__ pitch,   // [B,1,T]
    const float* __restrict__ energy,  // [B,1,T]
    const float* __restrict__ pw,      // [H,1,3]
    const float* __restrict__ pb,      // [H]
    const float* __restrict__ ew,      // [H,1,3]
    const float* __restrict__ eb,      // [H]
    const int*   __restrict__ durations,
    float* __restrict__ out)           // [B,MEL,H]
{
    const int t = blockIdx.x;
    const int b = blockIdx.y;
    const int q = threadIdx.x;

    int rep = durations[b * TT + t];
    if (rep <= 0) return;
    const int start = g_start[b * TT + t];
    const int end   = min(start + rep, MEL);
    if (start >= end) return;

    // enc row (one float4 per thread)
    const float4 e4 = *(const float4*)(enc + ((long long)b * TT + t) * HH + 4 * q);

    // conv windows (SAME, zero pad) — broadcast loads, L1-resident
    const float* pr = pitch  + (long long)b * TT;
    const float* er = energy + (long long)b * TT;
    const float pm1 = (t > 0)      ? pr[t - 1] : 0.f;
    const float p0  =                pr[t];
    const float pp1 = (t < TT - 1) ? pr[t + 1] : 0.f;
    const float em1 = (t > 0)      ? er[t - 1] : 0.f;
    const float e0  =                er[t];
    const float ep1 = (t < TT - 1) ? er[t + 1] : 0.f;

    // weights: [H][3] row-major -> 12 contiguous floats per float4-slot
    const float4* pwv = (const float4*)(pw + 12 * q);
    const float4 w0 = pwv[0], w1 = pwv[1], w2 = pwv[2];
    const float4* ewv = (const float4*)(ew + 12 * q);
    const float4 u0 = ewv[0], u1 = ewv[1], u2 = ewv[2];
    const float4 pbv = ((const float4*)pb)[q];
    const float4 ebv = ((const float4*)eb)[q];

    float4 res;
    res.x = e4.x + pbv.x + ebv.x
          + pm1 * w0.x + p0 * w0.y + pp1 * w0.z
          + em1 * u0.x + e0 * u0.y + ep1 * u0.z;
    res.y = e4.y + pbv.y + ebv.y
          + pm1 * w0.w + p0 * w1.x + pp1 * w1.y
          + em1 * u0.w + e0 * u1.x + ep1 * u1.y;
    res.z = e4.z + pbv.z + ebv.z
          + pm1 * w1.z + p0 * w1.w + pp1 * w2.x
          + em1 * u1.z + e0 * u1.w + ep1 * u2.x;
    res.w = e4.w + pbv.w + ebv.w
          + pm1 * w2.y + p0 * w2.z + pp1 * w2.w
          + em1 * u2.y + e0 * u2.z + ep1 * u2.w;

    // stream to the rep contiguous frames (pure coalesced STG.128)
    float4* dst = (float4*)out + ((long long)b * MEL + start) * H4 + q;
    #pragma unroll 4
    for (int j = start; j < end; ++j, dst += H4)
        *dst = res;
}

// ---------------------------------------------------------------------------
// Kernel 3: zero the masked tail [dec_len, MEL) per batch
// ---------------------------------------------------------------------------
__global__ void __launch_bounds__(256) zerofill_kernel(float4* __restrict__ out)
{
    const int b = blockIdx.y;
    const long long beg = (long long)g_dec[b] * H4;
    const long long end = (long long)MEL * H4;
    float4* base = out + (long long)b * MEL * H4;
    const float4 z = make_float4(0.f, 0.f, 0.f, 0.f);
    const long long stride = (long long)gridDim.x * blockDim.x;
    for (long long i = beg + (long long)blockIdx.x * blockDim.x + threadIdx.x;
         i < end; i += stride)
        base[i] = z;
}

// ---------------------------------------------------------------------------
// Tail: dec_lens appended to output as float values
// ---------------------------------------------------------------------------
__global__ void dec_tail_kernel(float* __restrict__ out_tail)
{
    const int b = threadIdx.x;
    if (b < BB) out_tail[b] = (float)g_dec[b];
}

extern "C" void kernel_launch(void* const* d_in, const int* in_sizes, int n_in,
                              void* d_out, int out_size)
{
    const float* enc    = (const float*)d_in[0];
    const float* pitch  = (const float*)d_in[1];
    const float* energy = (const float*)d_in[2];
    const float* pw     = (const float*)d_in[3];
    const float* pb     = (const float*)d_in[4];
    const float* ew     = (const float*)d_in[5];
    const float* eb     = (const float*)d_in[6];
    const int*   dur    = (const int*)d_in[7];
    float* out = (float*)d_out;

    prep_kernel<<<BB, TT>>>(dur);

    dim3 zgrid(32, BB);
    zerofill_kernel<<<zgrid, 256>>>((float4*)out);

    dim3 egrid(TT, BB);
    expand_kernel<<<egrid, 96>>>(enc, pitch, energy, pw, pb, ew, eb, dur, out);

    const long long mainN = (long long)BB * MEL * HH;    // 50,331,648
    if ((long long)out_size >= mainN + BB) {
        dec_tail_kernel<<<1, 32>>>(out + mainN);
    }
}

// round 4
// speedup vs baseline: 2.2736x; 1.1379x over previous
#include <cuda_runtime.h>
#include <cuda_bf16.h>

#define BB 32
#define TT 1024
#define HH 384
#define MEL 4096
#define H4 (HH/4)   // 96 float4 per frame
#define ZB 128      // zerofill blocks per batch (appended to expand grid)

// scratch (allocation-free rule: device globals)
__device__ int g_start[BB * TT];   // exclusive cumsum of reps
__device__ int g_dec[BB];

// ---------------------------------------------------------------------------
// Kernel 1: per-batch scan -> start offsets, dec_lens, and the output tail
// ---------------------------------------------------------------------------
__global__ void __launch_bounds__(TT) prep_kernel(const int* __restrict__ durations,
                                                  float* __restrict__ out_tail)
{
    const int b = blockIdx.x;
    const int t = threadIdx.x;
    const int lane = t & 31;
    const int wid  = t >> 5;

    int rep = durations[b * TT + t];   // PACE==1.0, ints: round(d/1)=d
    if (rep < 0) rep = 0;

    // warp inclusive scan
    int v = rep;
    #pragma unroll
    for (int o = 1; o < 32; o <<= 1) {
        int n = __shfl_up_sync(0xFFFFFFFFu, v, o);
        if (lane >= o) v += n;
    }

    __shared__ int wsum[32];
    __shared__ int s_total;
    if (lane == 31) wsum[wid] = v;
    __syncthreads();
    if (wid == 0) {
        int s = wsum[lane];
        #pragma unroll
        for (int o = 1; o < 32; o <<= 1) {
            int n = __shfl_up_sync(0xFFFFFFFFu, s, o);
            if (lane >= o) s += n;
        }
        wsum[lane] = s;
    }
    __syncthreads();

    const int csum = v + (wid > 0 ? wsum[wid - 1] : 0);  // inclusive
    if (t == TT - 1) s_total = csum;
    __syncthreads();

    g_start[b * TT + t] = csum - rep;                    // exclusive
    if (t == 0) {
        const int dlen = min(s_total, MEL);
        g_dec[b] = dlen;
        if (out_tail) out_tail[b] = (float)dlen;
    }
}

// ---------------------------------------------------------------------------
// Kernel 2: per-token conditioned vector streamed to its frames + pad zerofill.
// grid = (TT + ZB, BB), 96 threads (one float4 slot each).
//   blockIdx.x <  TT : token expansion
//   blockIdx.x >= TT : zero the [dec_len, MEL) tail (strided over ZB blocks)
// ---------------------------------------------------------------------------
__global__ void __launch_bounds__(96) expand_kernel(
    const float* __restrict__ enc,     // [B,T,H]
    const float* __restrict__ pitch,   // [B,1,T]
    const float* __restrict__ energy,  // [B,1,T]
    const float* __restrict__ pw,      // [H,1,3]
    const float* __restrict__ pb,      // [H]
    const float* __restrict__ ew,      // [H,1,3]
    const float* __restrict__ eb,      // [H]
    const int*   __restrict__ durations,
    float* __restrict__ out)           // [B,MEL,H]
{
    const int b = blockIdx.y;
    const int q = threadIdx.x;

    if (blockIdx.x >= TT) {
        // ---- zerofill path ----
        const int z = blockIdx.x - TT;
        const int dec = g_dec[b];
        const float4 zero = make_float4(0.f, 0.f, 0.f, 0.f);
        float4* base = (float4*)out + (long long)b * MEL * H4 + q;
        for (int j = dec + z; j < MEL; j += ZB)
            __stcs(base + (long long)j * H4, zero);
        return;
    }

    const int t = blockIdx.x;
    int rep = durations[b * TT + t];
    if (rep <= 0) return;
    const int start = g_start[b * TT + t];
    const int end   = min(start + rep, MEL);
    if (start >= end) return;

    // enc row (one float4 per thread)
    const float4 e4 = *(const float4*)(enc + ((long long)b * TT + t) * HH + 4 * q);

    // conv windows (SAME, zero pad) — broadcast loads, L1/L2-resident
    const float* pr = pitch  + (long long)b * TT;
    const float* er = energy + (long long)b * TT;
    const float pm1 = (t > 0)      ? pr[t - 1] : 0.f;
    const float p0  =                pr[t];
    const float pp1 = (t < TT - 1) ? pr[t + 1] : 0.f;
    const float em1 = (t > 0)      ? er[t - 1] : 0.f;
    const float e0  =                er[t];
    const float ep1 = (t < TT - 1) ? er[t + 1] : 0.f;

    // weights: [H][3] row-major -> 12 contiguous floats per float4-slot
    const float4* pwv = (const float4*)(pw + 12 * q);
    const float4 w0 = pwv[0], w1 = pwv[1], w2 = pwv[2];
    const float4* ewv = (const float4*)(ew + 12 * q);
    const float4 u0 = ewv[0], u1 = ewv[1], u2 = ewv[2];
    const float4 pbv = ((const float4*)pb)[q];
    const float4 ebv = ((const float4*)eb)[q];

    float4 res;
    res.x = e4.x + pbv.x + ebv.x
          + pm1 * w0.x + p0 * w0.y + pp1 * w0.z
          + em1 * u0.x + e0 * u0.y + ep1 * u0.z;
    res.y = e4.y + pbv.y + ebv.y
          + pm1 * w0.w + p0 * w1.x + pp1 * w1.y
          + em1 * u0.w + e0 * u1.x + ep1 * u1.y;
    res.z = e4.z + pbv.z + ebv.z
          + pm1 * w1.z + p0 * w1.w + pp1 * w2.x
          + em1 * u1.z + e0 * u1.w + ep1 * u2.x;
    res.w = e4.w + pbv.w + ebv.w
          + pm1 * w2.y + p0 * w2.z + pp1 * w2.w
          + em1 * u2.y + e0 * u2.z + ep1 * u2.w;

    // stream to the rep contiguous frames (coalesced STG.128, evict-first)
    float4* dst = (float4*)out + ((long long)b * MEL + start) * H4 + q;
    #pragma unroll 4
    for (int j = start; j < end; ++j, dst += H4)
        __stcs(dst, res);
}

extern "C" void kernel_launch(void* const* d_in, const int* in_sizes, int n_in,
                              void* d_out, int out_size)
{
    const float* enc    = (const float*)d_in[0];
    const float* pitch  = (const float*)d_in[1];
    const float* energy = (const float*)d_in[2];
    const float* pw     = (const float*)d_in[3];
    const float* pb     = (const float*)d_in[4];
    const float* ew     = (const float*)d_in[5];
    const float* eb     = (const float*)d_in[6];
    const int*   dur    = (const int*)d_in[7];
    float* out = (float*)d_out;

    const long long mainN = (long long)BB * MEL * HH;    // 50,331,648
    float* out_tail = ((long long)out_size >= mainN + BB) ? (out + mainN) : nullptr;

    prep_kernel<<<BB, TT>>>(dur, out_tail);

    dim3 egrid(TT + ZB, BB);
    expand_kernel<<<egrid, 96>>>(enc, pitch, energy, pw, pb, ew, eb, dur, out);
}